// round 2
// baseline (speedup 1.0000x reference)
#include <cuda_runtime.h>
#include <math.h>

// Circulant coefficients computed on-device (graph-capturable, no H2D).
__device__ __align__(16) float g_c[4];

__global__ void compute_filter_kernel(const float* __restrict__ amp,
                                      const float* __restrict__ phase) {
    if (threadIdx.x != 0 || blockIdx.x != 0) return;

    const double primes[24] = {2, 3, 5, 7, 11, 13, 17, 19, 23, 29, 31, 37,
                               41, 43, 47, 53, 59, 61, 67, 71, 73, 79, 83, 89};
    const double PI = 3.14159265358979323846;

    double fr_re[4] = {0, 0, 0, 0};
    double fr_im[4] = {0, 0, 0, 0};

    for (int j = 0; j < 24; j++) {
        double pf = primes[j] / 89.0 * PI;           // prime freq in [0, pi]
        double a  = (double)amp[j];
        double ph = (double)phase[j];
        double cre = a * cos(ph);
        double cim = a * sin(ph);
        for (int k = 0; k < 4; k++) {
            double fi = (double)k * 0.25 * PI;       // bin freq
            double d  = (fi - pf) / 0.1;
            double g  = exp(-0.5 * d * d);
            fr_re[k] += cre * g;
            fr_im[k] += cim * g;
        }
    }

    // normalization: max |fr| + 1e-8
    double mx = 0.0;
    for (int k = 0; k < 4; k++) {
        double m = sqrt(fr_re[k] * fr_re[k] + fr_im[k] * fr_im[k]);
        if (m > mx) mx = m;
    }
    mx += 1e-8;

    // h_d = Re( (1/4) sum_k filt_k * e^{i*pi*k*d/2} )
    for (int d = 0; d < 4; d++) {
        double s = 0.0;
        for (int k = 0; k < 4; k++) {
            double th = PI * 0.5 * (double)(k * d);
            s += fr_re[k] * cos(th) - fr_im[k] * sin(th);
        }
        g_c[d] = (float)(s * 0.25 / mx);
    }
}

// Each thread handles GPT consecutive float4 groups (front-batched loads for MLP).
#define GPT 2

__global__ void __launch_bounds__(256)
apply_circulant_kernel(const float4* __restrict__ x,
                       float4* __restrict__ y, int n_groups) {
    // Uniform broadcast load of the 4 coefficients (one 16B L2 hit).
    float4 c = *reinterpret_cast<const float4*>(g_c);
    const float c0 = c.x, c1 = c.y, c2 = c.z, c3 = c.w;

    long long base = (long long)(blockIdx.x * blockDim.x + threadIdx.x) * GPT;
    long long stride = (long long)gridDim.x * blockDim.x * GPT;

    for (; base < n_groups; base += stride) {
        float4 v[GPT];
        int cnt = 0;
        #pragma unroll
        for (int g = 0; g < GPT; g++) {
            long long i = base + g;
            if (i < n_groups) { v[g] = __ldg(&x[i]); cnt = g + 1; }
        }
        #pragma unroll
        for (int g = 0; g < GPT; g++) {
            if (g < cnt) {
                float4 r;
                // y_n = sum_m c[(n-m) & 3] * x_m  (circulant)
                r.x = c0 * v[g].x + c3 * v[g].y + c2 * v[g].z + c1 * v[g].w;
                r.y = c1 * v[g].x + c0 * v[g].y + c3 * v[g].z + c2 * v[g].w;
                r.z = c2 * v[g].x + c1 * v[g].y + c0 * v[g].z + c3 * v[g].w;
                r.w = c3 * v[g].x + c2 * v[g].y + c1 * v[g].z + c0 * v[g].w;
                y[base + g] = r;
            }
        }
    }
}

extern "C" void kernel_launch(void* const* d_in, const int* in_sizes, int n_in,
                              void* d_out, int out_size) {
    const float* qstate = (const float*)d_in[0];  // [4,2048,1024,4] f32
    const float* amp    = (const float*)d_in[1];  // [24]
    const float* phase  = (const float*)d_in[2];  // [24]
    float* out = (float*)d_out;

    compute_filter_kernel<<<1, 32>>>(amp, phase);

    int n_groups = out_size / 4;  // 8,388,608 quaternion groups
    int threads = 256;
    long long work_per_block = (long long)threads * GPT;
    int blocks = (int)((n_groups + work_per_block - 1) / work_per_block);
    apply_circulant_kernel<<<blocks, threads>>>(
        (const float4*)qstate, (float4*)out, n_groups);
}

// round 5
// speedup vs baseline: 1.4807x; 1.4807x over previous
#include <cuda_runtime.h>
#include <math.h>

// Circulant coefficients computed on-device (graph-capturable, no H2D).
__device__ __align__(16) float g_c[4];

__constant__ float c_primes[24] = {2, 3, 5, 7, 11, 13, 17, 19, 23, 29, 31, 37,
                                   41, 43, 47, 53, 59, 61, 67, 71, 73, 79, 83, 89};

// One warp: lanes 0-23 each handle one prime; shuffle-reduce the 4 complex bins.
__global__ void compute_filter_kernel(const float* __restrict__ amp,
                                      const float* __restrict__ phase) {
    const float PI = 3.14159265358979323846f;
    int lane = threadIdx.x;

    float re[4] = {0.f, 0.f, 0.f, 0.f};
    float im[4] = {0.f, 0.f, 0.f, 0.f};

    if (lane < 24) {
        float pf  = c_primes[lane] * (PI / 89.0f);   // prime freq in [0, pi]
        float a   = amp[lane];
        float ph  = phase[lane];
        float cre = a * cosf(ph);
        float cim = a * sinf(ph);
        #pragma unroll
        for (int k = 0; k < 4; k++) {
            float fi = (float)k * 0.25f * PI;
            float d  = (fi - pf) * 10.0f;            // /0.1
            float g  = __expf(-0.5f * d * d);
            re[k] = cre * g;
            im[k] = cim * g;
        }
    }

    // Warp reduction of the 8 accumulators.
    #pragma unroll
    for (int off = 16; off > 0; off >>= 1) {
        #pragma unroll
        for (int k = 0; k < 4; k++) {
            re[k] += __shfl_down_sync(0xffffffffu, re[k], off);
            im[k] += __shfl_down_sync(0xffffffffu, im[k], off);
        }
    }

    if (lane == 0) {
        float mx = 0.f;
        #pragma unroll
        for (int k = 0; k < 4; k++)
            mx = fmaxf(mx, sqrtf(re[k] * re[k] + im[k] * im[k]));
        mx += 1e-8f;
        float inv = 0.25f / mx;

        // h_d = Re( (1/4) sum_k filt_k * e^{i*pi*k*d/2} )
        #pragma unroll
        for (int d = 0; d < 4; d++) {
            float s = 0.f;
            #pragma unroll
            for (int k = 0; k < 4; k++) {
                float th = PI * 0.5f * (float)(k * d);
                s += re[k] * cosf(th) - im[k] * sinf(th);
            }
            g_c[d] = s * inv;
        }
    }
}

// Each block handles a contiguous tile of 256*GPT float4 groups; per-instruction
// accesses are fully coalesced (lane-contiguous 16B, 512B/warp).
#define GPT 4

__global__ void __launch_bounds__(256)
apply_circulant_kernel(const float4* __restrict__ x,
                       float4* __restrict__ y, int n_groups) {
    // Uniform broadcast load of the 4 coefficients.
    float4 c = *reinterpret_cast<const float4*>(g_c);
    const float c0 = c.x, c1 = c.y, c2 = c.z, c3 = c.w;

    int base = blockIdx.x * (256 * GPT) + threadIdx.x;

    if (base + 3 * 256 < n_groups) {
        // Fast path: whole tile in range, no predication, front-batched loads.
        float4 v[GPT];
        #pragma unroll
        for (int g = 0; g < GPT; g++)
            v[g] = __ldcs(&x[base + g * 256]);
        #pragma unroll
        for (int g = 0; g < GPT; g++) {
            float4 r;
            r.x = c0 * v[g].x + c3 * v[g].y + c2 * v[g].z + c1 * v[g].w;
            r.y = c1 * v[g].x + c0 * v[g].y + c3 * v[g].z + c2 * v[g].w;
            r.z = c2 * v[g].x + c1 * v[g].y + c0 * v[g].z + c3 * v[g].w;
            r.w = c3 * v[g].x + c2 * v[g].y + c1 * v[g].z + c0 * v[g].w;
            __stcs(&y[base + g * 256], r);
        }
    } else {
        #pragma unroll
        for (int g = 0; g < GPT; g++) {
            int i = base + g * 256;
            if (i < n_groups) {
                float4 v = __ldcs(&x[i]);
                float4 r;
                r.x = c0 * v.x + c3 * v.y + c2 * v.z + c1 * v.w;
                r.y = c1 * v.x + c0 * v.y + c3 * v.z + c2 * v.w;
                r.z = c2 * v.x + c1 * v.y + c0 * v.z + c3 * v.w;
                r.w = c3 * v.x + c2 * v.y + c1 * v.z + c0 * v.w;
                __stcs(&y[i], r);
            }
        }
    }
}

extern "C" void kernel_launch(void* const* d_in, const int* in_sizes, int n_in,
                              void* d_out, int out_size) {
    const float* qstate = (const float*)d_in[0];  // [4,2048,1024,4] f32
    const float* amp    = (const float*)d_in[1];  // [24]
    const float* phase  = (const float*)d_in[2];  // [24]
    float* out = (float*)d_out;

    compute_filter_kernel<<<1, 32>>>(amp, phase);

    int n_groups = out_size / 4;                  // 8,388,608 quaternion groups
    int per_block = 256 * GPT;
    int blocks = (n_groups + per_block - 1) / per_block;
    apply_circulant_kernel<<<blocks, 256>>>(
        (const float4*)qstate, (float4*)out, n_groups);
}

// round 7
// speedup vs baseline: 1.5083x; 1.0187x over previous
#include <cuda_runtime.h>
#include <math.h>

__constant__ float c_primes[24] = {2, 3, 5, 7, 11, 13, 17, 19, 23, 29, 31, 37,
                                   41, 43, 47, 53, 59, 61, 67, 71, 73, 79, 83, 89};

// Each block: warp 0 computes the 4 real circulant coefficients (FFT4 ->
// filter -> IFFT4 collapses to a real 4x4 circulant), then all 256 threads
// stream a contiguous tile of 256*GPT float4 groups with coalesced .cs
// accesses.
#define GPT 4

__global__ void __launch_bounds__(256)
fused_resonant_kernel(const float4* __restrict__ x,
                      float4* __restrict__ y,
                      const float* __restrict__ amp,
                      const float* __restrict__ phase,
                      int n_groups) {
    __shared__ __align__(16) float s_c[4];

    if (threadIdx.x < 32) {
        const float PI = 3.14159265358979323846f;
        int lane = threadIdx.x;

        float re[4] = {0.f, 0.f, 0.f, 0.f};
        float im[4] = {0.f, 0.f, 0.f, 0.f};

        if (lane < 24) {
            float pf  = c_primes[lane] * (PI / 89.0f);   // prime freq in [0, pi]
            float a   = __ldg(&amp[lane]);
            float ph  = __ldg(&phase[lane]);
            float cre = a * cosf(ph);
            float cim = a * sinf(ph);
            #pragma unroll
            for (int k = 0; k < 4; k++) {
                float fi = (float)k * 0.25f * PI;
                float d  = (fi - pf) * 10.0f;            // /0.1
                float g  = __expf(-0.5f * d * d);
                re[k] = cre * g;
                im[k] = cim * g;
            }
        }

        // Warp reduction of the 8 accumulators.
        #pragma unroll
        for (int off = 16; off > 0; off >>= 1) {
            #pragma unroll
            for (int k = 0; k < 4; k++) {
                re[k] += __shfl_down_sync(0xffffffffu, re[k], off);
                im[k] += __shfl_down_sync(0xffffffffu, im[k], off);
            }
        }

        if (lane == 0) {
            float mx = 0.f;
            #pragma unroll
            for (int k = 0; k < 4; k++)
                mx = fmaxf(mx, sqrtf(re[k] * re[k] + im[k] * im[k]));
            mx += 1e-8f;
            float inv = 0.25f / mx;

            // h_d = Re( (1/4) sum_k filt_k * e^{i*pi*k*d/2} )
            #pragma unroll
            for (int d = 0; d < 4; d++) {
                float s = 0.f;
                #pragma unroll
                for (int k = 0; k < 4; k++) {
                    float th = PI * 0.5f * (float)(k * d);
                    s += re[k] * cosf(th) - im[k] * sinf(th);
                }
                s_c[d] = s * inv;
            }
        }
    }
    __syncthreads();

    const float c0 = s_c[0], c1 = s_c[1], c2 = s_c[2], c3 = s_c[3];

    int base = blockIdx.x * (256 * GPT) + threadIdx.x;

    if (base + 3 * 256 < n_groups) {
        // Fast path: whole tile in range, no predication, front-batched loads.
        float4 v[GPT];
        #pragma unroll
        for (int g = 0; g < GPT; g++)
            v[g] = __ldcs(&x[base + g * 256]);
        #pragma unroll
        for (int g = 0; g < GPT; g++) {
            float4 r;
            // y_n = sum_m c[(n-m) & 3] * x_m  (circulant)
            r.x = c0 * v[g].x + c3 * v[g].y + c2 * v[g].z + c1 * v[g].w;
            r.y = c1 * v[g].x + c0 * v[g].y + c3 * v[g].z + c2 * v[g].w;
            r.z = c2 * v[g].x + c1 * v[g].y + c0 * v[g].z + c3 * v[g].w;
            r.w = c3 * v[g].x + c2 * v[g].y + c1 * v[g].z + c0 * v[g].w;
            __stcs(&y[base + g * 256], r);
        }
    } else {
        #pragma unroll
        for (int g = 0; g < GPT; g++) {
            int i = base + g * 256;
            if (i < n_groups) {
                float4 v = __ldcs(&x[i]);
                float4 r;
                r.x = c0 * v.x + c3 * v.y + c2 * v.z + c1 * v.w;
                r.y = c1 * v.x + c0 * v.y + c3 * v.z + c2 * v.w;
                r.z = c2 * v.x + c1 * v.y + c0 * v.z + c3 * v.w;
                r.w = c3 * v.x + c2 * v.y + c1 * v.z + c0 * v.w;
                __stcs(&y[i], r);
            }
        }
    }
}

extern "C" void kernel_launch(void* const* d_in, const int* in_sizes, int n_in,
                              void* d_out, int out_size) {
    const float* qstate = (const float*)d_in[0];  // [4,2048,1024,4] f32
    const float* amp    = (const float*)d_in[1];  // [24]
    const float* phase  = (const float*)d_in[2];  // [24]
    float* out = (float*)d_out;

    int n_groups = out_size / 4;                  // 8,388,608 quaternion groups
    int per_block = 256 * GPT;
    int blocks = (n_groups + per_block - 1) / per_block;
    fused_resonant_kernel<<<blocks, 256>>>(
        (const float4*)qstate, (float4*)out, amp, phase, n_groups);
}

// round 8
// speedup vs baseline: 1.5446x; 1.0241x over previous
#include <cuda_runtime.h>
#include <math.h>

__constant__ float c_primes[24] = {2, 3, 5, 7, 11, 13, 17, 19, 23, 29, 31, 37,
                                   41, 43, 47, 53, 59, 61, 67, 71, 73, 79, 83, 89};

// FFT4 -> pointwise filter -> IFFT4 -> Re() collapses to a real 4x4 circulant.
// Each block: front-batch GPT coalesced .cs loads FIRST, then warp 0 computes
// the 4 circulant coefficients while the loads are in flight (DRAM latency
// hides the prologue), then all threads FMA + store.
#define GPT 8

__global__ void __launch_bounds__(256)
fused_resonant_kernel(const float4* __restrict__ x,
                      float4* __restrict__ y,
                      const float* __restrict__ amp,
                      const float* __restrict__ phase,
                      int n_groups) {
    __shared__ __align__(16) float s_c[4];

    int base = blockIdx.x * (256 * GPT) + threadIdx.x;
    bool fast = (base + (GPT - 1) * 256 < n_groups);

    // 1) Issue streaming loads first (independent of coefficients).
    float4 v[GPT];
    if (fast) {
        #pragma unroll
        for (int g = 0; g < GPT; g++)
            v[g] = __ldcs(&x[base + g * 256]);
    }

    // 2) Filter prologue overlapped with the loads.
    if (threadIdx.x < 32) {
        const float PI = 3.14159265358979323846f;
        int lane = threadIdx.x;

        float re[4] = {0.f, 0.f, 0.f, 0.f};
        float im[4] = {0.f, 0.f, 0.f, 0.f};

        if (lane < 24) {
            float pf  = c_primes[lane] * (PI / 89.0f);   // prime freq in [0, pi]
            float a   = __ldg(&amp[lane]);
            float ph  = __ldg(&phase[lane]);
            float cre = a * __cosf(ph);
            float cim = a * __sinf(ph);
            #pragma unroll
            for (int k = 0; k < 4; k++) {
                float fi = (float)k * 0.25f * PI;
                float d  = (fi - pf) * 10.0f;            // /0.1
                float g  = __expf(-0.5f * d * d);
                re[k] = cre * g;
                im[k] = cim * g;
            }
        }

        #pragma unroll
        for (int off = 16; off > 0; off >>= 1) {
            #pragma unroll
            for (int k = 0; k < 4; k++) {
                re[k] += __shfl_down_sync(0xffffffffu, re[k], off);
                im[k] += __shfl_down_sync(0xffffffffu, im[k], off);
            }
        }

        if (lane == 0) {
            float mx = 0.f;
            #pragma unroll
            for (int k = 0; k < 4; k++)
                mx = fmaxf(mx, sqrtf(re[k] * re[k] + im[k] * im[k]));
            mx += 1e-8f;
            float inv = 0.25f / mx;

            // h_d = Re( (1/4) sum_k filt_k * e^{i*pi*k*d/2} )
            // e^{i*pi*k*d/2} cycles through {1, i, -1, -i}: use exact values.
            // h0 = (f0+f1+f2+f3)/4 ... expand with cos/sin of k*d*pi/2.
            #pragma unroll
            for (int d = 0; d < 4; d++) {
                float s = 0.f;
                #pragma unroll
                for (int k = 0; k < 4; k++) {
                    int q = (k * d) & 3;                 // quarter turns
                    float cth = (q == 0) ? 1.f : (q == 2) ? -1.f : 0.f;
                    float sth = (q == 1) ? 1.f : (q == 3) ? -1.f : 0.f;
                    s += re[k] * cth - im[k] * sth;
                }
                s_c[d] = s * inv;
            }
        }
    }
    __syncthreads();

    const float c0 = s_c[0], c1 = s_c[1], c2 = s_c[2], c3 = s_c[3];

    if (fast) {
        #pragma unroll
        for (int g = 0; g < GPT; g++) {
            float4 r;
            // y_n = sum_m c[(n-m) & 3] * x_m  (circulant)
            r.x = c0 * v[g].x + c3 * v[g].y + c2 * v[g].z + c1 * v[g].w;
            r.y = c1 * v[g].x + c0 * v[g].y + c3 * v[g].z + c2 * v[g].w;
            r.z = c2 * v[g].x + c1 * v[g].y + c0 * v[g].z + c3 * v[g].w;
            r.w = c3 * v[g].x + c2 * v[g].y + c1 * v[g].z + c0 * v[g].w;
            __stcs(&y[base + g * 256], r);
        }
    } else {
        #pragma unroll
        for (int g = 0; g < GPT; g++) {
            int i = base + g * 256;
            if (i < n_groups) {
                float4 t = __ldcs(&x[i]);
                float4 r;
                r.x = c0 * t.x + c3 * t.y + c2 * t.z + c1 * t.w;
                r.y = c1 * t.x + c0 * t.y + c3 * t.z + c2 * t.w;
                r.z = c2 * t.x + c1 * t.y + c0 * t.z + c3 * t.w;
                r.w = c3 * t.x + c2 * t.y + c1 * t.z + c0 * t.w;
                __stcs(&y[i], r);
            }
        }
    }
}

extern "C" void kernel_launch(void* const* d_in, const int* in_sizes, int n_in,
                              void* d_out, int out_size) {
    const float* qstate = (const float*)d_in[0];  // [4,2048,1024,4] f32
    const float* amp    = (const float*)d_in[1];  // [24]
    const float* phase  = (const float*)d_in[2];  // [24]
    float* out = (float*)d_out;

    int n_groups = out_size / 4;                  // 8,388,608 quaternion groups
    int per_block = 256 * GPT;
    int blocks = (n_groups + per_block - 1) / per_block;
    fused_resonant_kernel<<<blocks, 256>>>(
        (const float4*)qstate, (float4*)out, amp, phase, n_groups);
}

// round 11
// speedup vs baseline: 1.5490x; 1.0028x over previous
#include <cuda_runtime.h>
#include <math.h>

__constant__ float c_primes[24] = {2, 3, 5, 7, 11, 13, 17, 19, 23, 29, 31, 37,
                                   41, 43, 47, 53, 59, 61, 67, 71, 73, 79, 83, 89};

// FFT4 -> pointwise filter -> IFFT4 -> Re() collapses to a real 4x4 circulant.
// 512-thread blocks, GPT=4: tile of 2048 groups/block. Loads are issued FIRST,
// warp 0 computes the coefficients while they are in flight, then FMA + store.
#define GPT 4
#define NTHR 512

__global__ void __launch_bounds__(NTHR)
fused_resonant_kernel(const float4* __restrict__ x,
                      float4* __restrict__ y,
                      const float* __restrict__ amp,
                      const float* __restrict__ phase,
                      int n_groups) {
    __shared__ __align__(16) float s_c[4];

    int base = blockIdx.x * (NTHR * GPT) + threadIdx.x;
    bool fast = (base + (GPT - 1) * NTHR < n_groups);

    // 1) Issue streaming loads first (independent of coefficients).
    float4 v[GPT];
    if (fast) {
        #pragma unroll
        for (int g = 0; g < GPT; g++)
            v[g] = __ldcs(&x[base + g * NTHR]);
    }

    // 2) Filter prologue overlapped with the in-flight loads.
    if (threadIdx.x < 32) {
        const float PI = 3.14159265358979323846f;
        int lane = threadIdx.x;

        float re[4] = {0.f, 0.f, 0.f, 0.f};
        float im[4] = {0.f, 0.f, 0.f, 0.f};

        if (lane < 24) {
            float pf  = c_primes[lane] * (PI / 89.0f);   // prime freq in [0, pi]
            float a   = __ldg(&amp[lane]);
            float ph  = __ldg(&phase[lane]);
            float cre = a * __cosf(ph);
            float cim = a * __sinf(ph);
            #pragma unroll
            for (int k = 0; k < 4; k++) {
                float fi = (float)k * 0.25f * PI;
                float d  = (fi - pf) * 10.0f;            // /0.1
                float g  = __expf(-0.5f * d * d);
                re[k] = cre * g;
                im[k] = cim * g;
            }
        }

        #pragma unroll
        for (int off = 16; off > 0; off >>= 1) {
            #pragma unroll
            for (int k = 0; k < 4; k++) {
                re[k] += __shfl_down_sync(0xffffffffu, re[k], off);
                im[k] += __shfl_down_sync(0xffffffffu, im[k], off);
            }
        }

        if (lane == 0) {
            float mx = 0.f;
            #pragma unroll
            for (int k = 0; k < 4; k++)
                mx = fmaxf(mx, sqrtf(re[k] * re[k] + im[k] * im[k]));
            mx += 1e-8f;
            float inv = 0.25f / mx;

            // h_d = Re( (1/4) sum_k filt_k * i^{k*d} ): exact quarter turns.
            #pragma unroll
            for (int d = 0; d < 4; d++) {
                float s = 0.f;
                #pragma unroll
                for (int k = 0; k < 4; k++) {
                    int q = (k * d) & 3;
                    float cth = (q == 0) ? 1.f : (q == 2) ? -1.f : 0.f;
                    float sth = (q == 1) ? 1.f : (q == 3) ? -1.f : 0.f;
                    s += re[k] * cth - im[k] * sth;
                }
                s_c[d] = s * inv;
            }
        }
    }
    __syncthreads();

    const float c0 = s_c[0], c1 = s_c[1], c2 = s_c[2], c3 = s_c[3];

    if (fast) {
        #pragma unroll
        for (int g = 0; g < GPT; g++) {
            float4 r;
            // y_n = sum_m c[(n-m) & 3] * x_m  (circulant)
            r.x = c0 * v[g].x + c3 * v[g].y + c2 * v[g].z + c1 * v[g].w;
            r.y = c1 * v[g].x + c0 * v[g].y + c3 * v[g].z + c2 * v[g].w;
            r.z = c2 * v[g].x + c1 * v[g].y + c0 * v[g].z + c3 * v[g].w;
            r.w = c3 * v[g].x + c2 * v[g].y + c1 * v[g].z + c0 * v[g].w;
            __stcs(&y[base + g * NTHR], r);
        }
    } else {
        #pragma unroll
        for (int g = 0; g < GPT; g++) {
            int i = base + g * NTHR;
            if (i < n_groups) {
                float4 t = __ldcs(&x[i]);
                float4 r;
                r.x = c0 * t.x + c3 * t.y + c2 * t.z + c1 * t.w;
                r.y = c1 * t.x + c0 * t.y + c3 * t.z + c2 * t.w;
                r.z = c2 * t.x + c1 * t.y + c0 * t.z + c3 * t.w;
                r.w = c3 * t.x + c2 * t.y + c1 * t.z + c0 * t.w;
                __stcs(&y[i], r);
            }
        }
    }
}

extern "C" void kernel_launch(void* const* d_in, const int* in_sizes, int n_in,
                              void* d_out, int out_size) {
    const float* qstate = (const float*)d_in[0];  // [4,2048,1024,4] f32
    const float* amp    = (const float*)d_in[1];  // [24]
    const float* phase  = (const float*)d_in[2];  // [24]
    float* out = (float*)d_out;

    int n_groups = out_size / 4;                  // 8,388,608 quaternion groups
    int per_block = NTHR * GPT;
    int blocks = (n_groups + per_block - 1) / per_block;
    fused_resonant_kernel<<<blocks, NTHR>>>(
        (const float4*)qstate, (float4*)out, amp, phase, n_groups);
}